// round 1
// baseline (speedup 1.0000x reference)
#include <cuda_runtime.h>

#define NH      32
#define HD      128
#define QLR     1536
#define BSZ     8
#define SEQ     4096
#define NQ      (NH*HD)          // 4096 q columns
#define NSPLIT  4
#define TOKS    (SEQ/NSPLIT)     // 1024 tokens per split
#define NWARP   8                // warps per attention block
#define KTILES  6
#define KCHUNK  (QLR/KTILES)     // 256

// Scratch (device globals: no allocation allowed in kernel_launch)
__device__ float  g_qpart[KTILES][BSZ*NQ];      // split-K GEMM partials
__device__ float  g_q[BSZ*NQ];                  // q = h@W + b
__device__ float  g_pacc[BSZ*NH*NSPLIT*HD];     // split-KV weighted-V partials
__device__ float2 g_pml[BSZ*NH*NSPLIT];         // (max, sumexp) per split

// ---------------------------------------------------------------------------
// Kernel 1: split-K GEMM  q_part[kt][b][n] = sum_{k in tile} h[b][k]*W[k][n]
// grid (NQ/128, KTILES), block 128
// ---------------------------------------------------------------------------
__global__ void qgemm_kernel(const float* __restrict__ hq,
                             const float* __restrict__ W) {
    __shared__ float sh[BSZ][KCHUNK];
    const int k0 = blockIdx.y * KCHUNK;
    for (int idx = threadIdx.x; idx < BSZ * KCHUNK; idx += blockDim.x) {
        int b = idx / KCHUNK, k = idx % KCHUNK;
        sh[b][k] = hq[b * QLR + k0 + k];
    }
    __syncthreads();

    const int col = blockIdx.x * blockDim.x + threadIdx.x;
    float acc[BSZ];
#pragma unroll
    for (int b = 0; b < BSZ; b++) acc[b] = 0.0f;

    const float* Wp = W + (size_t)k0 * NQ + col;
#pragma unroll 4
    for (int k = 0; k < KCHUNK; k++) {
        float w = __ldg(&Wp[(size_t)k * NQ]);
#pragma unroll
        for (int b = 0; b < BSZ; b++) acc[b] += w * sh[b][k];
    }
#pragma unroll
    for (int b = 0; b < BSZ; b++)
        g_qpart[blockIdx.y][b * NQ + col] = acc[b];
}

// ---------------------------------------------------------------------------
// Kernel 2: reduce split-K partials + bias into g_q  (deterministic, no atomics)
// ---------------------------------------------------------------------------
__global__ void qreduce_kernel(const float* __restrict__ bq) {
    int i = blockIdx.x * blockDim.x + threadIdx.x;
    if (i >= BSZ * NQ) return;
    float s = bq[i & (NQ - 1)];
#pragma unroll
    for (int t = 0; t < KTILES; t++) s += g_qpart[t][i];
    g_q[i] = s;
}

// ---------------------------------------------------------------------------
// Kernel 3: split-KV flash attention partials.
// grid = BSZ*NH*NSPLIT blocks of 256 threads; warp-per-token.
// kv row for (b,s,h) is 256 contiguous floats: [0:128)=key, [128:256)=value.
// ---------------------------------------------------------------------------
__global__ void __launch_bounds__(NWARP * 32)
attn_partial_kernel(const float* __restrict__ kv) {
    const int bid   = blockIdx.x;
    const int split = bid % NSPLIT;
    const int bh    = bid / NSPLIT;       // b*NH + h
    const int h     = bh % NH;
    const int b     = bh / NH;
    const int warp  = threadIdx.x >> 5;
    const int lane  = threadIdx.x & 31;

    // q fragment: lane holds q[lane*4 .. lane*4+3]
    const float4 q4 = *(const float4*)&g_q[bh * HD + lane * 4];

    const float4* kv4 = (const float4*)kv;  // 64 float4 per (b,s,h) row
    const int s0  = split * TOKS;
    const int end = s0 + TOKS;

    float  m = -1e30f, l = 0.0f;
    float4 acc = make_float4(0.f, 0.f, 0.f, 0.f);

    // 2-deep pipeline: prefetch next token's k/v while processing current.
    int s = s0 + warp;
    size_t base = (((size_t)b * SEQ + s) * NH + h) * 64;
    float4 k4 = __ldg(&kv4[base + lane]);
    float4 v4 = __ldg(&kv4[base + 32 + lane]);

    for (; s < end; s += NWARP) {
        float4 kc = k4, vc = v4;
        int sn = s + NWARP;
        if (sn < end) {
            size_t bn = (((size_t)b * SEQ + sn) * NH + h) * 64;
            k4 = __ldg(&kv4[bn + lane]);
            v4 = __ldg(&kv4[bn + 32 + lane]);
        }
        // score = q . key (warp butterfly reduce)
        float sc = kc.x * q4.x + kc.y * q4.y + kc.z * q4.z + kc.w * q4.w;
#pragma unroll
        for (int o = 16; o > 0; o >>= 1)
            sc += __shfl_xor_sync(0xffffffffu, sc, o);

        // online softmax update
        float nm    = fmaxf(m, sc);
        float scale = __expf(m - nm);
        float p     = __expf(sc - nm);
        m = nm;
        l = l * scale + p;
        acc.x = acc.x * scale + p * vc.x;
        acc.y = acc.y * scale + p * vc.y;
        acc.z = acc.z * scale + p * vc.z;
        acc.w = acc.w * scale + p * vc.w;
    }

    // merge the NWARP per-warp partial softmaxes
    __shared__ float s_acc[NWARP][HD];
    __shared__ float s_m[NWARP], s_l[NWARP];
    s_acc[warp][lane * 4 + 0] = acc.x;
    s_acc[warp][lane * 4 + 1] = acc.y;
    s_acc[warp][lane * 4 + 2] = acc.z;
    s_acc[warp][lane * 4 + 3] = acc.w;
    if (lane == 0) { s_m[warp] = m; s_l[warp] = l; }
    __syncthreads();

    float M = -1e30f;
#pragma unroll
    for (int w = 0; w < NWARP; w++) M = fmaxf(M, s_m[w]);
    float L = 0.0f;
#pragma unroll
    for (int w = 0; w < NWARP; w++) L += __expf(s_m[w] - M) * s_l[w];

    const int d = threadIdx.x;
    if (d < HD) {
        float a = 0.0f;
#pragma unroll
        for (int w = 0; w < NWARP; w++) a += __expf(s_m[w] - M) * s_acc[w][d];
        g_pacc[(bh * NSPLIT + split) * HD + d] = a;
    }
    if (threadIdx.x == 0)
        g_pml[bh * NSPLIT + split] = make_float2(M, L);
}

// ---------------------------------------------------------------------------
// Kernel 4: combine split partials -> output[b][h*HD+d]
// grid = BSZ*NH blocks of HD threads
// ---------------------------------------------------------------------------
__global__ void attn_combine_kernel(float* __restrict__ out) {
    const int bh = blockIdx.x;
    const int d  = threadIdx.x;

    __shared__ float2 ml[NSPLIT];
    if (d < NSPLIT) ml[d] = g_pml[bh * NSPLIT + d];
    __syncthreads();

    float M = -1e30f;
#pragma unroll
    for (int i = 0; i < NSPLIT; i++) M = fmaxf(M, ml[i].x);
    float L = 0.0f;
#pragma unroll
    for (int i = 0; i < NSPLIT; i++) L += __expf(ml[i].x - M) * ml[i].y;

    float a = 0.0f;
#pragma unroll
    for (int i = 0; i < NSPLIT; i++)
        a += __expf(ml[i].x - M) * g_pacc[(bh * NSPLIT + i) * HD + d];

    out[bh * HD + d] = a / L;
}

// ---------------------------------------------------------------------------
extern "C" void kernel_launch(void* const* d_in, const int* in_sizes, int n_in,
                              void* d_out, int out_size) {
    const float* hq = (const float*)d_in[0];   // (8, 1536)
    const float* kv = (const float*)d_in[1];   // (8, 4096, 32, 256)
    const float* W  = (const float*)d_in[2];   // (1536, 4096)
    const float* bq = (const float*)d_in[3];   // (4096,)
    float* out = (float*)d_out;                // (8, 4096)

    qgemm_kernel<<<dim3(NQ / 128, KTILES), 128>>>(hq, W);
    qreduce_kernel<<<(BSZ * NQ + 255) / 256, 256>>>(bq);
    attn_partial_kernel<<<BSZ * NH * NSPLIT, NWARP * 32>>>(kv);
    attn_combine_kernel<<<BSZ * NH, HD>>>(out);
}

// round 3
// speedup vs baseline: 1.1252x; 1.1252x over previous
#include <cuda_runtime.h>

#define NH      32
#define HD      128
#define QLR     1536
#define BSZ     8
#define SEQ     4096
#define NQ      (NH*HD)            // 4096 q columns
#define NSPLIT  16
#define LOG2SPL 4
#define TOKS    (SEQ/NSPLIT)       // 256 tokens per work item
#define NWARP   8                  // warps per attention block
#define NPAIR   (TOKS/(2*NWARP))   // 16 pair-iterations per warp
#define NITEMS  (BSZ*NH*NSPLIT)    // 4096 work items
#define GRID_AT (148*4)            // persistent attention grid
#define KTILES  16
#define KCHUNK  (QLR/KTILES)       // 96
#define LOG2E   1.4426950408889634f
#define TOKF4   ((size_t)NH * 64)  // float4 stride between consecutive tokens

// Scratch (device globals: no allocation allowed in kernel_launch)
__device__ float  g_qpart[KTILES][BSZ*NQ];      // split-K GEMM partials
__device__ float  g_q[BSZ*NQ];                  // q = h@W + b (pre-scaled by log2e)
__device__ float  g_pacc[BSZ*NH*NSPLIT*HD];     // split-KV weighted-V partials
__device__ float2 g_pml[BSZ*NH*NSPLIT];         // (max, sumexp) per split (log2 domain)
__device__ int    g_work;                        // work-queue counter

// ---------------------------------------------------------------------------
// Kernel 1: split-K GEMM, float4 columns.
// grid (NQ/4/128 = 8, KTILES), block 128
// ---------------------------------------------------------------------------
__global__ void qgemm_kernel(const float* __restrict__ hq,
                             const float* __restrict__ W) {
    __shared__ float sh[BSZ][KCHUNK];
    const int k0 = blockIdx.y * KCHUNK;
    for (int idx = threadIdx.x; idx < BSZ * KCHUNK; idx += blockDim.x) {
        int b = idx / KCHUNK, k = idx % KCHUNK;
        sh[b][k] = hq[b * QLR + k0 + k];
    }
    __syncthreads();

    const int col4 = blockIdx.x * blockDim.x + threadIdx.x;  // float4 col idx
    const float4* W4 = (const float4*)W;                      // NQ/4 per row

    float4 acc[BSZ];
#pragma unroll
    for (int b = 0; b < BSZ; b++) acc[b] = make_float4(0.f, 0.f, 0.f, 0.f);

#pragma unroll 8
    for (int k = 0; k < KCHUNK; k++) {
        float4 w = __ldg(&W4[(size_t)(k0 + k) * (NQ / 4) + col4]);
#pragma unroll
        for (int b = 0; b < BSZ; b++) {
            float s = sh[b][k];
            acc[b].x += w.x * s; acc[b].y += w.y * s;
            acc[b].z += w.z * s; acc[b].w += w.w * s;
        }
    }
#pragma unroll
    for (int b = 0; b < BSZ; b++)
        ((float4*)&g_qpart[blockIdx.y][b * NQ])[col4] = acc[b];
}

// ---------------------------------------------------------------------------
// Kernel 2: reduce split-K partials + bias into g_q (scaled by log2e).
// Also resets the attention work-queue counter.
// ---------------------------------------------------------------------------
__global__ void qreduce_kernel(const float* __restrict__ bq) {
    if (blockIdx.x == 0 && threadIdx.x == 0) g_work = 0;
    int i = blockIdx.x * blockDim.x + threadIdx.x;   // float4 index
    if (i >= BSZ * NQ / 4) return;
    const float4* b4 = (const float4*)bq;
    float4 s = b4[i & (NQ / 4 - 1)];
#pragma unroll
    for (int t = 0; t < KTILES; t++) {
        float4 p = ((const float4*)g_qpart[t])[i];
        s.x += p.x; s.y += p.y; s.z += p.z; s.w += p.w;
    }
    s.x *= LOG2E; s.y *= LOG2E; s.z *= LOG2E; s.w *= LOG2E;
    ((float4*)g_q)[i] = s;
}

// ---------------------------------------------------------------------------
// Kernel 3: persistent split-KV flash attention, atomic work queue.
// Each item = (b,h,split) covering 256 tokens; warp-per-token-pair,
// one-pair-ahead prefetch (4 LDG.128 in flight / warp).
// kv row for (b,s,h) is 64 float4: [0:32)=key, [32:64)=value.
// Consecutive tokens are TOKF4 = NH*64 float4 apart.
// ---------------------------------------------------------------------------
__global__ void __launch_bounds__(NWARP * 32, 4)
attn_partial_kernel(const float* __restrict__ kv) {
    __shared__ int   s_item;
    __shared__ float s_acc[NWARP][HD];
    __shared__ float s_m[NWARP], s_l[NWARP];

    const int warp = threadIdx.x >> 5;
    const int lane = threadIdx.x & 31;
    const float4* kv4 = (const float4*)kv;

    for (;;) {
        if (threadIdx.x == 0) s_item = atomicAdd(&g_work, 1);
        __syncthreads();
        const int item = s_item;
        if (item >= NITEMS) break;

        const int split = item & (NSPLIT - 1);
        const int bh    = item >> LOG2SPL;    // b*NH + h
        const int h     = bh & (NH - 1);
        const int b     = bh >> 5;

        // q fragment (already log2e-scaled): lane holds q[lane*4..+3]
        const float4 q4 = *(const float4*)&g_q[bh * HD + lane * 4];

        float  m = -1e30f, l = 0.0f;
        float4 acc = make_float4(0.f, 0.f, 0.f, 0.f);

        // warp handles token pairs (s, s+1), pair stride 2*NWARP tokens
        const int s0 = split * TOKS + warp * 2;
        size_t base = (((size_t)b * SEQ + s0) * NH + h) * 64;
        const size_t PSTRIDE = (size_t)(2 * NWARP) * TOKF4;

        float4 k0 = __ldg(&kv4[base + lane]);
        float4 v0 = __ldg(&kv4[base + 32 + lane]);
        float4 k1 = __ldg(&kv4[base + TOKF4 + lane]);
        float4 v1 = __ldg(&kv4[base + TOKF4 + 32 + lane]);

#pragma unroll 4
        for (int p = 0; p < NPAIR; p++) {
            float4 kc0 = k0, vc0 = v0, kc1 = k1, vc1 = v1;
            if (p + 1 < NPAIR) {
                base += PSTRIDE;
                k0 = __ldg(&kv4[base + lane]);
                v0 = __ldg(&kv4[base + 32 + lane]);
                k1 = __ldg(&kv4[base + TOKF4 + lane]);
                v1 = __ldg(&kv4[base + TOKF4 + 32 + lane]);
            }
            float sc0 = kc0.x * q4.x + kc0.y * q4.y + kc0.z * q4.z + kc0.w * q4.w;
            float sc1 = kc1.x * q4.x + kc1.y * q4.y + kc1.z * q4.z + kc1.w * q4.w;
#pragma unroll
            for (int o = 16; o > 0; o >>= 1) {
                sc0 += __shfl_xor_sync(0xffffffffu, sc0, o);
                sc1 += __shfl_xor_sync(0xffffffffu, sc1, o);
            }
            float nm    = fmaxf(m, fmaxf(sc0, sc1));
            float scale = exp2f(m - nm);
            float p0    = exp2f(sc0 - nm);
            float p1    = exp2f(sc1 - nm);
            m = nm;
            l = l * scale + p0 + p1;
            acc.x = acc.x * scale + p0 * vc0.x + p1 * vc1.x;
            acc.y = acc.y * scale + p0 * vc0.y + p1 * vc1.y;
            acc.z = acc.z * scale + p0 * vc0.z + p1 * vc1.z;
            acc.w = acc.w * scale + p0 * vc0.w + p1 * vc1.w;
        }

        // merge the NWARP per-warp partial softmaxes
        s_acc[warp][lane * 4 + 0] = acc.x;
        s_acc[warp][lane * 4 + 1] = acc.y;
        s_acc[warp][lane * 4 + 2] = acc.z;
        s_acc[warp][lane * 4 + 3] = acc.w;
        if (lane == 0) { s_m[warp] = m; s_l[warp] = l; }
        __syncthreads();

        float M = -1e30f;
#pragma unroll
        for (int w = 0; w < NWARP; w++) M = fmaxf(M, s_m[w]);
        float L = 0.0f;
#pragma unroll
        for (int w = 0; w < NWARP; w++) L += exp2f(s_m[w] - M) * s_l[w];

        const int d = threadIdx.x;
        if (d < HD) {
            float a = 0.0f;
#pragma unroll
            for (int w = 0; w < NWARP; w++) a += exp2f(s_m[w] - M) * s_acc[w][d];
            g_pacc[(bh * NSPLIT + split) * HD + d] = a;
        }
        if (threadIdx.x == 0)
            g_pml[bh * NSPLIT + split] = make_float2(M, L);

        __syncthreads();   // protect s_item / s_* reuse across items
    }
}

// ---------------------------------------------------------------------------
// Kernel 4: combine split partials -> output[b][h*HD+d]
// grid = BSZ*NH blocks of HD threads
// ---------------------------------------------------------------------------
__global__ void attn_combine_kernel(float* __restrict__ out) {
    const int bh = blockIdx.x;
    const int d  = threadIdx.x;

    __shared__ float2 ml[NSPLIT];
    if (d < NSPLIT) ml[d] = g_pml[bh * NSPLIT + d];
    __syncthreads();

    float M = -1e30f;
#pragma unroll
    for (int i = 0; i < NSPLIT; i++) M = fmaxf(M, ml[i].x);
    float L = 0.0f;
#pragma unroll
    for (int i = 0; i < NSPLIT; i++) L += exp2f(ml[i].x - M) * ml[i].y;

    float a = 0.0f;
#pragma unroll
    for (int i = 0; i < NSPLIT; i++)
        a += exp2f(ml[i].x - M) * g_pacc[(bh * NSPLIT + i) * HD + d];

    out[bh * HD + d] = a / L;
}

// ---------------------------------------------------------------------------
extern "C" void kernel_launch(void* const* d_in, const int* in_sizes, int n_in,
                              void* d_out, int out_size) {
    const float* hq = (const float*)d_in[0];   // (8, 1536)
    const float* kv = (const float*)d_in[1];   // (8, 4096, 32, 256)
    const float* W  = (const float*)d_in[2];   // (1536, 4096)
    const float* bq = (const float*)d_in[3];   // (4096,)
    float* out = (float*)d_out;                // (8, 4096)

    qgemm_kernel<<<dim3(NQ / 4 / 128, KTILES), 128>>>(hq, W);
    qreduce_kernel<<<(BSZ * NQ / 4 + 255) / 256, 256>>>(bq);
    attn_partial_kernel<<<GRID_AT, NWARP * 32>>>(kv);
    attn_combine_kernel<<<BSZ * NH, HD>>>(out);
}